// round 1
// baseline (speedup 1.0000x reference)
#include <cuda_runtime.h>
#include <mma.h>
#include <cstdint>

using namespace nvcuda;

#define IN_F  4096
#define OUT_F 4096
#define NFAC  3

// ---------------- scratch (device globals: no allocation allowed) ----------
__device__ float g_Q[NFAC * 64 * 64 * 64];     // Cayley results, 3 MB
__device__ int   g_pinv[NFAC * IN_F];
__device__ float g_w0[(size_t)OUT_F * IN_F];   // 64 MB
__device__ float g_w1[(size_t)OUT_F * IN_F];   // 64 MB

// ---------------- Cayley: Q = (I-S)(I+S)^-1 via GJ on [I-S | I+S] ----------
// Solves (I-S) Y = (I+S)  ->  Y = Q^T.  (I-S) has SPD symmetric part (= I),
// so Gauss-Jordan without pivoting is stable.
__global__ void cayley_kernel(const float* __restrict__ R_all)
{
    __shared__ float aug[64][129];
    const int m   = blockIdx.x;             // 0..191
    const float* R = R_all + (size_t)m * 4096;
    const int tid = threadIdx.x;            // 256 threads

    for (int idx = tid; idx < 4096; idx += 256) {
        int i = idx >> 6, j = idx & 63;
        float s = 0.5f * (R[i * 64 + j] - R[j * 64 + i]);
        float d = (i == j) ? 1.0f : 0.0f;
        aug[i][j]      = d - s;   // B   = I - S
        aug[i][64 + j] = d + s;   // B^T = I + S
    }
    __syncthreads();

    const int r  = tid >> 2;       // row owned (4 threads per row)
    const int c0 = tid & 3;
    for (int k = 0; k < 64; k++) {
        float inv = 1.0f / aug[k][k];      // read pivot (stable after prior sync)
        __syncthreads();                   // everyone has read pivot
        if (tid < 32) {
            #pragma unroll
            for (int i = 0; i < 4; i++) aug[k][tid + 32 * i] *= inv;
        }
        __syncthreads();                   // row k normalized
        float f = aug[r][k];
        __syncthreads();                   // factors read before col k changes
        if (r != k) {
            #pragma unroll
            for (int i = 0; i < 32; i++) {
                int c = c0 + 4 * i;
                aug[r][c] -= f * aug[k][c];
            }
        }
        __syncthreads();                   // iteration complete
    }

    float* Qm = g_Q + (size_t)m * 4096;
    for (int idx = tid; idx < 4096; idx += 256) {
        int a = idx >> 6, b = idx & 63;
        Qm[a * 64 + b] = aug[b][64 + a];   // Q = Y^T
    }
}

// ---------------- inverse permutation ----------------
__global__ void pinv_kernel(const int* __restrict__ perm)
{
    int f = blockIdx.y;
    int j = blockIdx.x * 256 + threadIdx.x;   // grid (16,3)
    g_pinv[f * IN_F + perm[f * IN_F + j]] = j;
}

// ---------------- apply one butterfly factor to W (cols), optional scale ----
// Wout[r, pinv[d*64+a]] = sum_b Q[f,d,a,b] * Win[r, pinv[d*64+b]]   (* s[r])
__global__ void rot_kernel(const float* __restrict__ Win, float* __restrict__ Wout,
                           int factor, const float* __restrict__ s)
{
    __shared__ float Qs[64][65];
    __shared__ float Ts[64][65];
    __shared__ int   cs[64];

    const int d   = blockIdx.x;   // block index 0..63
    const int rg  = blockIdx.y;   // row group 0..63
    const int tid = threadIdx.x;  // 256

    const float* Qm = g_Q + ((size_t)factor * 64 + d) * 4096;
    for (int idx = tid; idx < 4096; idx += 256)
        Qs[idx >> 6][idx & 63] = Qm[idx];
    if (tid < 64) cs[tid] = g_pinv[factor * IN_F + d * 64 + tid];
    __syncthreads();

    const int row0 = rg * 64;
    for (int idx = tid; idx < 4096; idx += 256) {
        int rr = idx >> 6, b = idx & 63;
        Ts[rr][b] = Win[(size_t)(row0 + rr) * IN_F + cs[b]];  // 32-run contiguous -> coalesced
    }
    __syncthreads();

    const int a  = tid & 63;
    const int r0 = tid >> 6;      // 0..3
    float acc[16];
    #pragma unroll
    for (int j = 0; j < 16; j++) acc[j] = 0.0f;

    for (int b = 0; b < 64; b++) {
        float q = Qs[a][b];
        #pragma unroll
        for (int j = 0; j < 16; j++)
            acc[j] += q * Ts[r0 + 4 * j][b];
    }

    const int col = cs[a];
    #pragma unroll
    for (int j = 0; j < 16; j++) {
        int rr = row0 + r0 + 4 * j;
        float v = acc[j];
        if (s) v *= s[rr];
        Wout[(size_t)rr * IN_F + col] = v;
    }
}

// ---------------- TF32 wmma GEMM: C[M,N] = A[M,K] * B[N,K]^T ----------------
#define BM 128
#define BN 128
#define BK 32
#define LDA_S 40   // BK + 8 pad: stride 160B (32B-aligned rows for wmma.load)

__global__ __launch_bounds__(256) void gemm_tf32(
    const float* __restrict__ A, const float* __restrict__ B,
    float* __restrict__ C, int M, int N, int K)
{
    extern __shared__ float smem[];
    float* As = smem;                     // [2][BM*LDA_S]
    float* Bs = smem + 2 * BM * LDA_S;    // [2][BN*LDA_S]

    const int tid  = threadIdx.x;
    const int warp = tid >> 5;
    const int wm   = warp >> 2;   // 0..1
    const int wn   = warp & 3;    // 0..3
    const size_t m0 = (size_t)blockIdx.y * BM;
    const size_t n0 = (size_t)blockIdx.x * BN;

    wmma::fragment<wmma::accumulator, 16, 16, 8, float> acc[4][2];
    #pragma unroll
    for (int i = 0; i < 4; i++)
        #pragma unroll
        for (int j = 0; j < 2; j++) wmma::fill_fragment(acc[i][j], 0.0f);

    float4 ra[4], rb[4];

    auto fetch = [&](int k0) {
        #pragma unroll
        for (int t = 0; t < 4; t++) {
            int idx = tid + 256 * t;
            int r = idx >> 3, c = (idx & 7) << 2;
            ra[t] = *reinterpret_cast<const float4*>(A + (m0 + r) * K + k0 + c);
            rb[t] = *reinterpret_cast<const float4*>(B + (n0 + r) * K + k0 + c);
        }
    };
    auto stage = [&](int buf) {
        #pragma unroll
        for (int t = 0; t < 4; t++) {
            int idx = tid + 256 * t;
            int r = idx >> 3, c = (idx & 7) << 2;
            float4 va = ra[t], vb = rb[t];
            va.x = wmma::__float_to_tf32(va.x);  va.y = wmma::__float_to_tf32(va.y);
            va.z = wmma::__float_to_tf32(va.z);  va.w = wmma::__float_to_tf32(va.w);
            vb.x = wmma::__float_to_tf32(vb.x);  vb.y = wmma::__float_to_tf32(vb.y);
            vb.z = wmma::__float_to_tf32(vb.z);  vb.w = wmma::__float_to_tf32(vb.w);
            *reinterpret_cast<float4*>(As + buf * BM * LDA_S + r * LDA_S + c) = va;
            *reinterpret_cast<float4*>(Bs + buf * BN * LDA_S + r * LDA_S + c) = vb;
        }
    };

    fetch(0);
    stage(0);
    __syncthreads();

    const int nk = K / BK;   // 128
    int buf = 0;
    for (int kt = 0; kt < nk; kt++) {
        if (kt + 1 < nk) fetch((kt + 1) * BK);

        #pragma unroll
        for (int kk = 0; kk < 4; kk++) {
            wmma::fragment<wmma::matrix_a, 16, 16, 8, wmma::precision::tf32, wmma::row_major> af[4];
            wmma::fragment<wmma::matrix_b, 16, 16, 8, wmma::precision::tf32, wmma::col_major> bf[2];
            #pragma unroll
            for (int mi = 0; mi < 4; mi++)
                wmma::load_matrix_sync(af[mi],
                    As + buf * BM * LDA_S + (wm * 64 + mi * 16) * LDA_S + kk * 8, LDA_S);
            #pragma unroll
            for (int ni = 0; ni < 2; ni++)
                wmma::load_matrix_sync(bf[ni],
                    Bs + buf * BN * LDA_S + (wn * 32 + ni * 16) * LDA_S + kk * 8, LDA_S);
            #pragma unroll
            for (int mi = 0; mi < 4; mi++)
                #pragma unroll
                for (int ni = 0; ni < 2; ni++)
                    wmma::mma_sync(acc[mi][ni], af[mi], bf[ni], acc[mi][ni]);
        }

        if (kt + 1 < nk) {
            stage(buf ^ 1);      // buf^1 fully consumed one iteration ago
            __syncthreads();
            buf ^= 1;
        }
    }

    #pragma unroll
    for (int mi = 0; mi < 4; mi++)
        #pragma unroll
        for (int ni = 0; ni < 2; ni++)
            wmma::store_matrix_sync(
                C + (m0 + wm * 64 + mi * 16) * N + n0 + wn * 32 + ni * 16,
                acc[mi][ni], N, wmma::mem_row_major);
}

// ---------------- bias epilogue ----------------
__global__ void bias_kernel(float* __restrict__ C, const float* __restrict__ bias)
{
    int i = blockIdx.x * 256 + threadIdx.x;      // float4 index, exact grid
    float4 v = reinterpret_cast<float4*>(C)[i];
    float4 b = reinterpret_cast<const float4*>(bias)[i & 1023];  // 1024 float4 / row
    v.x += b.x; v.y += b.y; v.z += b.z; v.w += b.w;
    reinterpret_cast<float4*>(C)[i] = v;
}

// ---------------- launch ----------------
extern "C" void kernel_launch(void* const* d_in, const int* in_sizes, int n_in,
                              void* d_out, int out_size)
{
    const float* x      = (const float*)d_in[0];
    const float* weight = (const float*)d_in[1];
    const float* bias   = (const float*)d_in[2];
    const float* boft_R = (const float*)d_in[3];
    const float* boft_s = (const float*)d_in[4];
    const int*   perm   = (const int*)d_in[5];
    float* out = (float*)d_out;

    float *w0, *w1;
    cudaGetSymbolAddress((void**)&w0, g_w0);
    cudaGetSymbolAddress((void**)&w1, g_w1);

    cayley_kernel<<<192, 256>>>(boft_R);
    pinv_kernel<<<dim3(16, 3), 256>>>(perm);

    rot_kernel<<<dim3(64, 64), 256>>>(weight, w0, 0, nullptr);
    rot_kernel<<<dim3(64, 64), 256>>>(w0,     w1, 1, nullptr);
    rot_kernel<<<dim3(64, 64), 256>>>(w1,     w0, 2, boft_s);   // fold boft_s

    const int smem_bytes = 2 * (BM * LDA_S + BN * LDA_S) * sizeof(float);  // 81920
    cudaFuncSetAttribute(gemm_tf32, cudaFuncAttributeMaxDynamicSharedMemorySize, smem_bytes);
    gemm_tf32<<<dim3(4096 / BN, 16384 / BM), 256, smem_bytes>>>(
        x, w0, out, 16384, 4096, 4096);

    bias_kernel<<<(16384 * 4096 / 4) / 256, 256>>>(out, bias);
}

// round 3
// speedup vs baseline: 5.5676x; 5.5676x over previous
#include <cuda_runtime.h>
#include <cuda_fp16.h>
#include <cstdint>

#define IN_F  4096
#define OUT_F 4096
#define NFAC  3

// ---------------- scratch (device globals; allocation forbidden) -----------
__device__ __align__(1024) float  g_Q[NFAC * 64 * 64 * 64];
__device__ int    g_pinv[NFAC * IN_F];
__device__ __align__(1024) float  g_w0[(size_t)OUT_F * IN_F];        // 64 MB
__device__ __align__(1024) float  g_w1[(size_t)OUT_F * IN_F];        // 64 MB
__device__ __align__(1024) __half g_wh[(size_t)OUT_F * IN_F];        // 32 MB
__device__ __align__(1024) __half g_xh[(size_t)8 * 2048 * IN_F];     // 128 MB

// ---------------- helpers ---------------------------------------------------
__device__ __forceinline__ uint32_t smem_u32(const void* p) {
    uint32_t a;
    asm("{ .reg .u64 t; cvta.to.shared.u64 t, %1; cvt.u32.u64 %0, t; }" : "=r"(a) : "l"(p));
    return a;
}
#define CP_ASYNC16(dst, src) \
    asm volatile("cp.async.cg.shared.global [%0], [%1], 16;" :: "r"(dst), "l"(src) : "memory")
#define CP_COMMIT()  asm volatile("cp.async.commit_group;" ::: "memory")
#define CP_WAIT1()   asm volatile("cp.async.wait_group 1;" ::: "memory")

#define LDSM4(r, addr) \
    asm volatile("ldmatrix.sync.aligned.m8n8.x4.shared.b16 {%0,%1,%2,%3}, [%4];" \
        : "=r"((r)[0]), "=r"((r)[1]), "=r"((r)[2]), "=r"((r)[3]) : "r"(addr))

#define MMA16816(c, a, b0v, b1v) \
    asm volatile("mma.sync.aligned.m16n8k16.row.col.f32.f16.f16.f32 " \
        "{%0,%1,%2,%3},{%4,%5,%6,%7},{%8,%9},{%0,%1,%2,%3};" \
        : "+f"((c)[0]), "+f"((c)[1]), "+f"((c)[2]), "+f"((c)[3]) \
        : "r"((a)[0]), "r"((a)[1]), "r"((a)[2]), "r"((a)[3]), "r"(b0v), "r"(b1v))

// ---------------- Cayley: Q = (I-S)(I+S)^-1 via GJ on [I-S | I+S] ----------
__global__ void cayley_kernel(const float* __restrict__ R_all)
{
    __shared__ float aug[64][129];
    const int m   = blockIdx.x;
    const float* R = R_all + (size_t)m * 4096;
    const int tid = threadIdx.x;

    for (int idx = tid; idx < 4096; idx += 256) {
        int i = idx >> 6, j = idx & 63;
        float s = 0.5f * (R[i * 64 + j] - R[j * 64 + i]);
        float d = (i == j) ? 1.0f : 0.0f;
        aug[i][j]      = d - s;
        aug[i][64 + j] = d + s;
    }
    __syncthreads();

    const int r  = tid >> 2;
    const int c0 = tid & 3;
    for (int k = 0; k < 64; k++) {
        float inv = 1.0f / aug[k][k];
        __syncthreads();
        if (tid < 32) {
            #pragma unroll
            for (int i = 0; i < 4; i++) aug[k][tid + 32 * i] *= inv;
        }
        __syncthreads();
        float f = aug[r][k];
        __syncthreads();
        if (r != k) {
            #pragma unroll
            for (int i = 0; i < 32; i++) {
                int c = c0 + 4 * i;
                aug[r][c] -= f * aug[k][c];
            }
        }
        __syncthreads();
    }

    float* Qm = g_Q + (size_t)m * 4096;
    for (int idx = tid; idx < 4096; idx += 256) {
        int a = idx >> 6, b = idx & 63;
        Qm[a * 64 + b] = aug[b][64 + a];
    }
}

// ---------------- inverse permutation ----------------
__global__ void pinv_kernel(const int* __restrict__ perm)
{
    int f = blockIdx.y;
    int j = blockIdx.x * 256 + threadIdx.x;
    g_pinv[f * IN_F + perm[f * IN_F + j]] = j;
}

// ---------------- x -> fp16 ----------------
__global__ void convert_x(const float4* __restrict__ in, uint4* __restrict__ out)
{
    int i = blockIdx.x * 256 + threadIdx.x;        // one 16B output per thread
    float4 a = in[2 * i], b = in[2 * i + 1];
    __half2 h0 = __floats2half2_rn(a.x, a.y);
    __half2 h1 = __floats2half2_rn(a.z, a.w);
    __half2 h2 = __floats2half2_rn(b.x, b.y);
    __half2 h3 = __floats2half2_rn(b.z, b.w);
    uint4 v;
    v.x = *(uint32_t*)&h0; v.y = *(uint32_t*)&h1;
    v.z = *(uint32_t*)&h2; v.w = *(uint32_t*)&h3;
    out[i] = v;
}

// ---------------- one butterfly factor applied to W columns ----------------
// Wout[r, cs[a]] = sum_b Q[f,d,a,b] * Win[r, cs[b]]
// Last pass (s != null): multiply by s[row] and emit fp16 into Wh.
__global__ __launch_bounds__(256) void rot_kernel(
    const float* __restrict__ Win, float* __restrict__ Wout,
    __half* __restrict__ Wh, int factor, const float* __restrict__ s)
{
    __shared__ float Qs[64][68];
    __shared__ float Ts[64][68];
    __shared__ int   cs[64];

    const int d   = blockIdx.x;
    const int rg  = blockIdx.y;
    const int tid = threadIdx.x;

    const float* Qm = g_Q + ((size_t)factor * 64 + d) * 4096;
    #pragma unroll
    for (int i = 0; i < 4; i++) {
        int q = tid + 256 * i;
        int row = q >> 4, c4 = (q & 15) * 4;
        *(float4*)&Qs[row][c4] = *(const float4*)&Qm[row * 64 + c4];
    }
    if (tid < 64) cs[tid] = g_pinv[factor * IN_F + d * 64 + tid];
    __syncthreads();

    const int row0 = rg * 64;
    #pragma unroll
    for (int i = 0; i < 4; i++) {
        int q = tid + 256 * i;
        int rr = q >> 4, b0 = (q & 15) * 4;
        // pinv moves 32-aligned runs of 32 -> float4 gather is contiguous
        *(float4*)&Ts[rr][b0] = *(const float4*)&Win[(size_t)(row0 + rr) * IN_F + cs[b0]];
    }
    __syncthreads();

    const int a  = tid & 63;
    const int r0 = tid >> 6;
    float acc[16];
    #pragma unroll
    for (int j = 0; j < 16; j++) acc[j] = 0.0f;

    for (int b4 = 0; b4 < 16; b4++) {
        float4 q = *(const float4*)&Qs[a][b4 * 4];
        #pragma unroll
        for (int j = 0; j < 16; j++) {
            float4 t = *(const float4*)&Ts[r0 * 16 + j][b4 * 4];
            acc[j] += q.x * t.x + q.y * t.y + q.z * t.z + q.w * t.w;
        }
    }

    const int col = cs[a];
    #pragma unroll
    for (int j = 0; j < 16; j++) {
        int rr = row0 + r0 * 16 + j;
        if (s) Wh[(size_t)rr * IN_F + col] = __float2half_rn(acc[j] * s[rr]);
        else   Wout[(size_t)rr * IN_F + col] = acc[j];
    }
}

// ---------------- fp16 mma.sync GEMM: C[16384,4096] = A * B^T + bias -------
// A [M,K] half row-major, B [N,K] half row-major. BM=BN=128, BK=64 halves.
#define BKH 64
#define AST 16384                       // 128 x 64 halves
#define STG 32768                       // A + B per stage
#define STAGES 3
#define SMEM_TOTAL (STAGES * STG)       // 98304

__global__ __launch_bounds__(256, 2) void gemm_hmma(
    const __half* __restrict__ A, const __half* __restrict__ B,
    const float* __restrict__ bias, float* __restrict__ C)
{
    extern __shared__ char smem[];
    const uint32_t sb = smem_u32(smem);
    const int tid = threadIdx.x;
    const int wid = tid >> 5, lid = tid & 31;
    const int wm  = wid & 3, wn = wid >> 2;       // 4 x 2 warp grid; warp tile 32x64
    const int m0  = blockIdx.y * 128;
    const int n0  = blockIdx.x * 128;

    float acc[2][8][4];
    #pragma unroll
    for (int i = 0; i < 2; i++)
        #pragma unroll
        for (int j = 0; j < 8; j++)
            #pragma unroll
            for (int k = 0; k < 4; k++) acc[i][j][k] = 0.0f;

    auto load_stage = [&](int st, int kt) {
        const uint32_t ab = sb + st * STG;
        const uint32_t bb = ab + AST;
        const __half* Ag = A + (size_t)m0 * IN_F + kt * BKH;
        const __half* Bg = B + (size_t)n0 * IN_F + kt * BKH;
        #pragma unroll
        for (int i = 0; i < 4; i++) {
            int q = tid + 256 * i;                 // 1024 chunks of 16B
            int r = q >> 3, c = q & 7;
            CP_ASYNC16(ab + r * 128 + ((c ^ (r & 7)) << 4), Ag + (size_t)r * IN_F + c * 8);
        }
        #pragma unroll
        for (int i = 0; i < 4; i++) {
            int q = tid + 256 * i;
            int r = q >> 3, c = q & 7;
            CP_ASYNC16(bb + r * 128 + ((c ^ (r & 7)) << 4), Bg + (size_t)r * IN_F + c * 8);
        }
    };

    load_stage(0, 0); CP_COMMIT();
    load_stage(1, 1); CP_COMMIT();

    const int lrow = (lid & 7) + ((lid >> 3) & 1) * 8;   // 0..15 within 16-row tile
    const int lkhi = (lid >> 4) & 1;                     // k-chunk select

    const int NK = IN_F / BKH;    // 64
    for (int kt = 0; kt < NK; kt++) {
        CP_WAIT1();
        __syncthreads();
        const uint32_t as = sb + (kt % STAGES) * STG;
        const uint32_t bs = as + AST;

        #pragma unroll
        for (int kk = 0; kk < 4; kk++) {
            uint32_t afr[2][4];
            #pragma unroll
            for (int mi = 0; mi < 2; mi++) {
                int ar = wm * 32 + mi * 16 + lrow;
                uint32_t ad = as + ar * 128 + ((((kk << 1) | lkhi) ^ (ar & 7)) << 4);
                LDSM4(afr[mi], ad);
            }
            uint32_t bfr[4][4];
            #pragma unroll
            for (int g = 0; g < 4; g++) {
                int br = wn * 64 + g * 16 + lrow;
                uint32_t bd = bs + br * 128 + ((((kk << 1) | lkhi) ^ (br & 7)) << 4);
                LDSM4(bfr[g], bd);
            }
            #pragma unroll
            for (int mi = 0; mi < 2; mi++)
                #pragma unroll
                for (int g = 0; g < 4; g++) {
                    MMA16816(acc[mi][2 * g],     afr[mi], bfr[g][0], bfr[g][2]);
                    MMA16816(acc[mi][2 * g + 1], afr[mi], bfr[g][1], bfr[g][3]);
                }
        }

        if (kt + 2 < NK) load_stage((kt + 2) % STAGES, kt + 2);
        CP_COMMIT();    // commit every iter so wait_group count stays aligned
    }

    // epilogue: fused bias, float2 stores (32B per quad -> sector aligned)
    const int mrow = lid >> 2;
    const int ncl  = (lid & 3) * 2;
    #pragma unroll
    for (int g = 0; g < 8; g++) {
        int n = n0 + wn * 64 + g * 8 + ncl;
        float2 bv = *(const float2*)&bias[n];
        #pragma unroll
        for (int mi = 0; mi < 2; mi++) {
            int m = m0 + wm * 32 + mi * 16 + mrow;
            float2 v0 = { acc[mi][g][0] + bv.x, acc[mi][g][1] + bv.y };
            float2 v1 = { acc[mi][g][2] + bv.x, acc[mi][g][3] + bv.y };
            *(float2*)&C[(size_t)m * OUT_F + n]       = v0;
            *(float2*)&C[(size_t)(m + 8) * OUT_F + n] = v1;
        }
    }
}

// ---------------- launch ----------------
extern "C" void kernel_launch(void* const* d_in, const int* in_sizes, int n_in,
                              void* d_out, int out_size)
{
    const float* x      = (const float*)d_in[0];
    const float* weight = (const float*)d_in[1];
    const float* bias   = (const float*)d_in[2];
    const float* boft_R = (const float*)d_in[3];
    const float* boft_s = (const float*)d_in[4];
    const int*   perm   = (const int*)d_in[5];
    float* out = (float*)d_out;

    float *w0, *w1; __half *wh, *xh;
    cudaGetSymbolAddress((void**)&w0, g_w0);
    cudaGetSymbolAddress((void**)&w1, g_w1);
    cudaGetSymbolAddress((void**)&wh, g_wh);
    cudaGetSymbolAddress((void**)&xh, g_xh);

    cayley_kernel<<<192, 256>>>(boft_R);
    pinv_kernel<<<dim3(16, 3), 256>>>(perm);
    convert_x<<<32768, 256>>>((const float4*)x, (uint4*)xh);

    rot_kernel<<<dim3(64, 64), 256>>>(weight, w0, nullptr, 0, nullptr);
    rot_kernel<<<dim3(64, 64), 256>>>(w0,     w1, nullptr, 1, nullptr);
    rot_kernel<<<dim3(64, 64), 256>>>(w1, nullptr, wh,     2, boft_s);

    cudaFuncSetAttribute(gemm_hmma, cudaFuncAttributeMaxDynamicSharedMemorySize, SMEM_TOTAL);
    gemm_hmma<<<dim3(OUT_F / 128, 16384 / 128), 256, SMEM_TOTAL>>>(xh, wh, bias, out);
}